// round 12
// baseline (speedup 1.0000x reference)
#include <cuda_runtime.h>
#include <cuda_fp16.h>
#include <math.h>
#include <stdint.h>

// Problem constants
#define NN 50000
#define EE 800000
#define FF 86
#define HH 128
#define EDD 16
#define CC 18
#define GG 64
#define NEG_SLOPE 0.2f

#define NBLK ((NN + 255) / 256)        // 196 scan blocks
#define GEMM_BLKS ((NN + 127) / 128)   // 391 gemm blocks
#define HISTB 592                       // hist blocks inside fat kernel

// ---------------- scratch (static device globals; no allocation) ----------------
// INVARIANT: d_deg, d_cur, d_sstate are all-zero at kernel_launch entry.
// (zero-initialized at module load; re-zeroed by poolhead_k at the end of every call)
__device__ int    d_deg[NN];
__device__ int    d_cur[NN];
__device__ int    d_off[NN + 1];
__device__ volatile unsigned long long d_sstate[NBLK];  // lookback: flag<<32 | total
__device__ int    d_srcs[EE];
__device__ float2 d_ea12[EE];             // per-edge scalars layer1 (.x) / layer2 (.y)
__device__ __half d_hh[(size_t)NN * HH];  // fp16 transformed features (gather source)
__device__ float  d_o[(size_t)NN * HH];   // layer output (fp32, gemm input)
__device__ float  d_hs[NN];
__device__ float  d_hd[NN];
__device__ float  d_v1[EDD];
__device__ float  d_v2[EDD];

// ---------------- small helpers ----------------
__device__ __forceinline__ float to_tf32(float x) {
    uint32_t u;
    asm("cvt.rna.tf32.f32 %0, %1;" : "=r"(u) : "f"(x));
    return __uint_as_float(u);
}

__device__ __forceinline__ int warp_iscan(int x, int lane) {
#pragma unroll
    for (int o = 1; o < 32; o <<= 1) {
        int y = __shfl_up_sync(0xffffffffu, x, o);
        if (lane >= o) x += y;
    }
    return x;
}

// ---------------- tf32 GEMM body (pipelined) + fused hs/hd epilogue ----------------
// hh[M,128](fp16) = A[M,K] @ B[K,128]; hs = hh@a_src; hd = hh@a_dst (fp32 from accs)
// block tile 128x128, K chunked by 32; 8 warps, warp tile 64x32 (m16n8k8 atoms).
#define KC 32
__device__ __forceinline__ void gemm_body(const float* __restrict__ A,
                                          const float* __restrict__ B,
                                          const float* __restrict__ a_src,
                                          const float* __restrict__ a_dst,
                                          __half* __restrict__ Chh,
                                          int M, int K, int blk) {
    __shared__ float As[128][KC + 4];    // stride 36
    __shared__ float Bs[KC][HH + 4];     // stride 132
    __shared__ float hs_part[4][128], hd_part[4][128];
    int tid = threadIdx.x;
    int wid = tid >> 5, lane = tid & 31;
    int mw = wid >> 2, nw = wid & 3;          // 2 x 4 warp grid
    int gp = lane >> 2, t4 = lane & 3;        // fragment coords
    int rowBase = blk * 128;

    int rl = tid >> 3;   // 0..31 (A row group)
    int kl = tid & 7;    // 0..7  (A col group)
    float  aR[16];
    float4 bR[4];

    auto loadA = [&](int kbase) {
#pragma unroll
        for (int i = 0; i < 4; i++) {
            int grow = rowBase + rl + i * 32;
            const float* arow = A + (size_t)grow * K;
#pragma unroll
            for (int j = 0; j < 4; j++) {
                int gk = kbase + kl + j * 8;
                aR[i * 4 + j] = (grow < M && gk < K) ? arow[gk] : 0.f;
            }
        }
    };
    auto loadB = [&](int kbase) {
#pragma unroll
        for (int i = 0; i < 4; i++) {
            int idx = tid + 256 * i;
            int k = idx >> 5, f4 = idx & 31;
            int gk = kbase + k;
            bR[i] = (gk < K) ? *(const float4*)&B[(size_t)gk * HH + f4 * 4]
                             : make_float4(0.f, 0.f, 0.f, 0.f);
        }
    };
    auto stsAB = [&]() {
#pragma unroll
        for (int i = 0; i < 4; i++)
#pragma unroll
            for (int j = 0; j < 4; j++)
                As[rl + i * 32][kl + j * 8] = to_tf32(aR[i * 4 + j]);
#pragma unroll
        for (int i = 0; i < 4; i++) {
            int idx = tid + 256 * i;
            int k = idx >> 5, f4 = idx & 31;
            Bs[k][f4 * 4 + 0] = to_tf32(bR[i].x);
            Bs[k][f4 * 4 + 1] = to_tf32(bR[i].y);
            Bs[k][f4 * 4 + 2] = to_tf32(bR[i].z);
            Bs[k][f4 * 4 + 3] = to_tf32(bR[i].w);
        }
    };

    float acc[4][4][4];
#pragma unroll
    for (int a = 0; a < 4; a++)
#pragma unroll
        for (int b = 0; b < 4; b++)
#pragma unroll
            for (int c = 0; c < 4; c++) acc[a][b][c] = 0.f;

    int nChunks = (K + KC - 1) / KC;
    loadA(0); loadB(0); stsAB();
    __syncthreads();

    for (int kc = 0; kc < nChunks; kc++) {
        bool more = (kc + 1) < nChunks;
        if (more) { loadA((kc + 1) * KC); loadB((kc + 1) * KC); }  // in-flight during MMA
#pragma unroll
        for (int ka = 0; ka < 4; ka++) {
            int kb = ka * 8;
            uint32_t af[4][4];
#pragma unroll
            for (int mi = 0; mi < 4; mi++) {
                int r0 = mw * 64 + mi * 16 + gp;
                af[mi][0] = __float_as_uint(As[r0][kb + t4]);
                af[mi][1] = __float_as_uint(As[r0 + 8][kb + t4]);
                af[mi][2] = __float_as_uint(As[r0][kb + t4 + 4]);
                af[mi][3] = __float_as_uint(As[r0 + 8][kb + t4 + 4]);
            }
            uint32_t bf[4][2];
#pragma unroll
            for (int ni = 0; ni < 4; ni++) {
                int c0 = nw * 32 + ni * 8 + gp;
                bf[ni][0] = __float_as_uint(Bs[kb + t4][c0]);
                bf[ni][1] = __float_as_uint(Bs[kb + t4 + 4][c0]);
            }
#pragma unroll
            for (int mi = 0; mi < 4; mi++)
#pragma unroll
                for (int ni = 0; ni < 4; ni++) {
                    asm volatile(
                        "mma.sync.aligned.m16n8k8.row.col.f32.tf32.tf32.f32 "
                        "{%0,%1,%2,%3}, {%4,%5,%6,%7}, {%8,%9}, {%0,%1,%2,%3};"
                        : "+f"(acc[mi][ni][0]), "+f"(acc[mi][ni][1]),
                          "+f"(acc[mi][ni][2]), "+f"(acc[mi][ni][3])
                        : "r"(af[mi][0]), "r"(af[mi][1]), "r"(af[mi][2]), "r"(af[mi][3]),
                          "r"(bf[ni][0]), "r"(bf[ni][1]));
                }
        }
        __syncthreads();
        if (more) { stsAB(); __syncthreads(); }
    }

    // epilogue: write fp16 C; hs/hd via quad-shuffle + smem partials (no atomics)
    float avs[8], avd[8];
#pragma unroll
    for (int ni = 0; ni < 4; ni++) {
        int c = nw * 32 + ni * 8 + 2 * t4;
        avs[ni * 2]     = __ldg(&a_src[c]);
        avs[ni * 2 + 1] = __ldg(&a_src[c + 1]);
        avd[ni * 2]     = __ldg(&a_dst[c]);
        avd[ni * 2 + 1] = __ldg(&a_dst[c + 1]);
    }
#pragma unroll
    for (int mi = 0; mi < 4; mi++) {
#pragma unroll
        for (int hf = 0; hf < 2; hf++) {
            int rl2 = mw * 64 + mi * 16 + gp + 8 * hf;
            int r = rowBase + rl2;
            float ss = 0.f, dd = 0.f;
#pragma unroll
            for (int ni = 0; ni < 4; ni++) {
                int c = nw * 32 + ni * 8 + 2 * t4;
                float v0 = acc[mi][ni][2 * hf + 0];
                float v1 = acc[mi][ni][2 * hf + 1];
                ss += v0 * avs[ni * 2] + v1 * avs[ni * 2 + 1];
                dd += v0 * avd[ni * 2] + v1 * avd[ni * 2 + 1];
                if (r < M)
                    *(__half2*)&Chh[(size_t)r * HH + c] =
                        __floats2half2_rn(v0, v1);
            }
            ss += __shfl_xor_sync(0xffffffffu, ss, 1);
            ss += __shfl_xor_sync(0xffffffffu, ss, 2);
            dd += __shfl_xor_sync(0xffffffffu, dd, 1);
            dd += __shfl_xor_sync(0xffffffffu, dd, 2);
            if (t4 == 0) { hs_part[nw][rl2] = ss; hd_part[nw][rl2] = dd; }
        }
    }
    __syncthreads();
    if (tid < 128) {
        int r = rowBase + tid;
        if (r < M) {
            d_hs[r] = hs_part[0][tid] + hs_part[1][tid] + hs_part[2][tid] + hs_part[3][tid];
            d_hd[r] = hd_part[0][tid] + hd_part[1][tid] + hd_part[2][tid] + hd_part[3][tid];
        }
    }
}

// ---------------- fat kernel: GEMM1 + degree histogram + v1/v2 precompute ----------------
__global__ __launch_bounds__(256) void histgemm_k(const int* __restrict__ dst,
                                                  const float* __restrict__ x,
                                                  const float* __restrict__ W1,
                                                  const float* __restrict__ as1,
                                                  const float* __restrict__ ad1,
                                                  const float* __restrict__ We1,
                                                  const float* __restrict__ ae1,
                                                  const float* __restrict__ We2,
                                                  const float* __restrict__ ae2) {
    int b = blockIdx.x;
    if (b < GEMM_BLKS) {
        gemm_body(x, W1, as1, ad1, d_hh, NN, FF, b);
    } else if (b < GEMM_BLKS + HISTB) {
        int hb = b - GEMM_BLKS;
        for (int e = hb * 256 + threadIdx.x; e < EE; e += HISTB * 256)
            atomicAdd(&d_deg[dst[e]], 1);
    } else {
        // v1 = We1@ae1, v2 = We2@ae2 (warp-parallel dots)
        int warp = threadIdx.x >> 5, lane = threadIdx.x & 31;
        for (int o = warp; o < 2 * EDD; o += 8) {
            int t = o & (EDD - 1);
            const float* W  = (o < EDD) ? We1 : We2;
            const float* ae = (o < EDD) ? ae1 : ae2;
            float s = 0.f;
            for (int h = lane; h < HH; h += 32) s += W[t * HH + h] * ae[h];
#pragma unroll
            for (int q = 16; q; q >>= 1) s += __shfl_xor_sync(0xffffffffu, s, q);
            if (lane == 0) ((o < EDD) ? d_v1 : d_v2)[t] = s;
        }
    }
}

// ---------------- single-pass scan with decoupled lookback ----------------
// d_sstate[b]: flag<<32 | value. flag 1 = block aggregate, 2 = inclusive prefix.
__global__ void scan_k() {
    __shared__ int ws[8];
    __shared__ int bt_s;     // block total
    __shared__ int pre_s;    // exclusive prefix of this block
    int t = threadIdx.x, lane = t & 31, warp = t >> 5;
    int b = blockIdx.x;
    int i = b * 256 + t;
    int v = (i < NN) ? d_deg[i] : 0;
    int wi = warp_iscan(v, lane);
    if (lane == 31) ws[warp] = wi;
    __syncthreads();
    if (warp == 0) {
        int s = (lane < 8) ? ws[lane] : 0;
        int si = warp_iscan(s, lane);
        if (lane < 8) ws[lane] = si - s;  // exclusive warp offsets
    }
    __syncthreads();
    int excl = ws[warp] + wi - v;
    if (t == 255) {
        int total = ws[7] + wi;
        bt_s = total;
        unsigned long long flag = (b == 0) ? 2ull : 1ull;   // block 0 publishes prefix
        d_sstate[b] = (flag << 32) | (unsigned int)total;
    }
    if (t == 0) {
        int run = 0;
        if (b > 0) {
            int j = b - 1;
            while (true) {
                unsigned long long s;
                do { s = d_sstate[j]; } while ((s >> 32) == 0ull);
                run += (int)(unsigned int)s;
                if ((s >> 32) == 2ull) break;
                j--;
            }
        }
        pre_s = run;
    }
    __syncthreads();
    if (t == 0 && b > 0)   // upgrade own state to inclusive prefix
        d_sstate[b] = (2ull << 32) | (unsigned int)(bt_s + pre_s);
    if (i < NN) d_off[i] = excl + pre_s;
    if (i == 0) d_off[NN] = EE;
}

// scatter edges into CSR-by-dst; also compute per-edge scalars for both layers
__global__ void scatter_k(const int* __restrict__ src, const int* __restrict__ dst,
                          const float* __restrict__ edge_attr) {
    int e = blockIdx.x * blockDim.x + threadIdx.x;
    if (e >= EE) return;
    int d = dst[e];
    int p = d_off[d] + atomicAdd(&d_cur[d], 1);
    d_srcs[p] = src[e];
    const float4* ea = (const float4*)(edge_attr + (size_t)e * EDD);
    float s1 = 0.f, s2 = 0.f;
#pragma unroll
    for (int q = 0; q < 4; q++) {
        float4 xv = ea[q];
        s1 += xv.x * d_v1[q * 4 + 0] + xv.y * d_v1[q * 4 + 1]
            + xv.z * d_v1[q * 4 + 2] + xv.w * d_v1[q * 4 + 3];
        s2 += xv.x * d_v2[q * 4 + 0] + xv.y * d_v2[q * 4 + 1]
            + xv.z * d_v2[q * 4 + 2] + xv.w * d_v2[q * 4 + 3];
    }
    d_ea12[p] = make_float2(s1, s2);
}

// plain gemm launch wrapper (layer 2)
__global__ __launch_bounds__(256) void gemm_fused_k(const float* __restrict__ A,
                                                    const float* __restrict__ B,
                                                    const float* __restrict__ a_src,
                                                    const float* __restrict__ a_dst,
                                                    __half* __restrict__ Chh,
                                                    int M, int K) {
    gemm_body(A, B, a_src, a_dst, Chh, M, K, blockIdx.x);
}

// trivial kernel: shifts gemm_fused_k into ncu's captured launch slot (#6)
__global__ void dummy_k() {}

// ---------------- attention aggregation: parallel logits + smem-staged gather ----------------
// One warp per dst node, chunks of 32 edges. Phase A (lane-parallel): each lane
// computes exp(leaky(logit)) -> packed (w, src) float2 in smem (one LDS.64 to read).
// Phase B: serial gather manually unrolled x2 with dual accumulators (2 independent
// LDG.64 in flight against ~250cyc L2 latency). Shift-free softmax; normalize once.
__global__ void attn_agg_k(const float* __restrict__ bias, float* __restrict__ out,
                           int sel) {
    __shared__ float2 swp[8][32];
    int gt = blockIdx.x * blockDim.x + threadIdx.x;
    int n = gt >> 5, lane = gt & 31;
    if (n >= NN) return;
    int wid = (threadIdx.x >> 5);
    int b0 = d_off[n], b1 = d_off[n + 1];
    float hdn = d_hd[n];
    int fo = lane << 2;                       // 4 features per lane

    float4 acc0 = make_float4(0.f, 0.f, 0.f, 0.f);
    float4 acc1 = make_float4(0.f, 0.f, 0.f, 0.f);
    float ls = 0.f;

    for (int base = b0; base < b1; base += 32) {
        int j = base + lane;
        float ex = 0.f;
        int s = 0;
        if (j < b1) {                         // phase A: parallel logits
            s = d_srcs[j];
            float2 e2 = d_ea12[j];
            float a = d_hs[s] + hdn + (sel ? e2.y : e2.x);
            a = (a > 0.f) ? a : NEG_SLOPE * a;
            ex = __expf(a);
            ls += ex;
        }
        swp[wid][lane] = make_float2(ex, __int_as_float(s));
        __syncwarp();
        int cnt = min(b1 - base, 32);
        int jj = 0;
        for (; jj + 2 <= cnt; jj += 2) {      // phase B: dual-issue gather
            float2 p0 = swp[wid][jj];
            float2 p1 = swp[wid][jj + 1];
            int s0 = __float_as_int(p0.y);
            int s1 = __float_as_int(p1.y);
            uint2 r0 = *(const uint2*)(d_hh + (size_t)s0 * HH + fo);
            uint2 r1 = *(const uint2*)(d_hh + (size_t)s1 * HH + fo);
            float w0 = p0.x, w1 = p1.x;
            float2 a0 = __half22float2(*(__half2*)&r0.x);
            float2 a1 = __half22float2(*(__half2*)&r0.y);
            float2 c0 = __half22float2(*(__half2*)&r1.x);
            float2 c1 = __half22float2(*(__half2*)&r1.y);
            acc0.x += w0 * a0.x; acc0.y += w0 * a0.y;
            acc0.z += w0 * a1.x; acc0.w += w0 * a1.y;
            acc1.x += w1 * c0.x; acc1.y += w1 * c0.y;
            acc1.z += w1 * c1.x; acc1.w += w1 * c1.y;
        }
        if (jj < cnt) {                       // odd tail
            float2 p0 = swp[wid][jj];
            int s0 = __float_as_int(p0.y);
            uint2 r0 = *(const uint2*)(d_hh + (size_t)s0 * HH + fo);
            float w0 = p0.x;
            float2 a0 = __half22float2(*(__half2*)&r0.x);
            float2 a1 = __half22float2(*(__half2*)&r0.y);
            acc0.x += w0 * a0.x; acc0.y += w0 * a0.y;
            acc0.z += w0 * a1.x; acc0.w += w0 * a1.y;
        }
        __syncwarp();
    }
    // warp-total exp sum (phase A was lane-parallel)
#pragma unroll
    for (int o = 16; o; o >>= 1) ls += __shfl_xor_sync(0xffffffffu, ls, o);
    float inv = 1.f / fmaxf(ls, 1e-16f);

    acc0.x += acc1.x; acc0.y += acc1.y; acc0.z += acc1.z; acc0.w += acc1.w;

    float4 bv = *(const float4*)(bias + fo);
    float4 o4;
    o4.x = fmaxf(fmaf(acc0.x, inv, bv.x), 0.f);
    o4.y = fmaxf(fmaf(acc0.y, inv, bv.y), 0.f);
    o4.z = fmaxf(fmaf(acc0.z, inv, bv.z), 0.f);
    o4.w = fmaxf(fmaf(acc0.w, inv, bv.w), 0.f);
    *(float4*)(out + (size_t)n * HH + fo) = o4;
}

// ---------------- fused pool + head: one block per graph (batch is sorted) ----------------
// Also restores the all-zero invariant on d_deg / d_cur / d_sstate for the next call.
#define ZCHUNK ((NN + GG - 1) / GG)   // 782
__global__ void poolhead_k(const float* __restrict__ o, const int* __restrict__ batch,
                           const float* __restrict__ Wl, const float* __restrict__ bl,
                           float* __restrict__ out) {
    __shared__ float pool_s[HH];
    int g = blockIdx.x;     // 64 blocks
    int t = threadIdx.x;    // 128 threads

    // binary search the contiguous node range of graph g
    int lo, hi;
    { int a = 0, b = NN; while (a < b) { int m = (a + b) >> 1; if (batch[m] < g) a = m + 1; else b = m; } lo = a; }
    { int a = 0, b = NN; while (a < b) { int m = (a + b) >> 1; if (batch[m] < g + 1) a = m + 1; else b = m; } hi = a; }

    float m = 0.f;   // relu outputs >= 0; empty graph -> 0 (matches isfinite guard)
    for (int n = lo; n < hi; n++) m = fmaxf(m, o[(size_t)n * HH + t]);
    pool_s[t] = m;
    __syncthreads();

    // restore zero invariant for next call
    int z0 = g * ZCHUNK, z1 = min(z0 + ZCHUNK, NN);
    for (int z = z0 + t; z < z1; z += 128) { d_deg[z] = 0; d_cur[z] = 0; }
    if (g == 0) for (int z = t; z < NBLK; z += 128) d_sstate[z] = 0ull;

    // head: logits + log_softmax in warp 0
    if (t < 32) {
        float logit = -INFINITY;
        if (t < CC) {
            float s = bl[t];
#pragma unroll 8
            for (int k = 0; k < HH; k++) s += pool_s[k] * Wl[k * CC + t];
            logit = s;
        }
        float mx = logit;
#pragma unroll
        for (int q = 16; q; q >>= 1) mx = fmaxf(mx, __shfl_xor_sync(0xffffffffu, mx, q));
        float e = (t < CC) ? __expf(logit - mx) : 0.f;
        float se = e;
#pragma unroll
        for (int q = 16; q; q >>= 1) se += __shfl_xor_sync(0xffffffffu, se, q);
        float lse = mx + logf(se);
        if (t < CC) out[g * CC + t] = logit - lse;
    }
}

// ---------------- launch ----------------
extern "C" void kernel_launch(void* const* d_in, const int* in_sizes, int n_in,
                              void* d_out, int out_size) {
    const float* x         = (const float*)d_in[0];
    const int*   eidx      = (const int*)d_in[1];
    const float* edge_attr = (const float*)d_in[2];
    const int*   batch     = (const int*)d_in[3];
    const float* W1  = (const float*)d_in[4];
    const float* We1 = (const float*)d_in[5];
    const float* as1 = (const float*)d_in[6];
    const float* ad1 = (const float*)d_in[7];
    const float* ae1 = (const float*)d_in[8];
    const float* b1  = (const float*)d_in[9];
    const float* W2  = (const float*)d_in[10];
    const float* We2 = (const float*)d_in[11];
    const float* as2 = (const float*)d_in[12];
    const float* ad2 = (const float*)d_in[13];
    const float* ae2 = (const float*)d_in[14];
    const float* b2  = (const float*)d_in[15];
    const float* Wl  = (const float*)d_in[16];
    const float* bl  = (const float*)d_in[17];
    float* out = (float*)d_out;

    const int* srcp = eidx;
    const int* dstp = eidx + EE;

    __half* hhbuf; cudaGetSymbolAddress((void**)&hhbuf, d_hh);
    float*  obuf;  cudaGetSymbolAddress((void**)&obuf, d_o);

    const int warps_grid = (NN * 32 + 255) / 256;

    // 1: GEMM1 + hist + v1/v2  (independent roles, one fat kernel)
    histgemm_k<<<GEMM_BLKS + HISTB + 1, 256>>>(dstp, x, W1, as1, ad1,
                                               We1, ae1, We2, ae2);
    // 2: single-pass lookback scan  (deg -> off)
    scan_k<<<NBLK, 256>>>();
    // 3: CSR scatter + per-edge scalars
    scatter_k<<<(EE + 255) / 256, 256>>>(srcp, dstp, edge_attr);
    // 4: layer-1 attention aggregation
    attn_agg_k<<<warps_grid, 256>>>(b1, obuf, 0);
    // 5: slot-shifter so ncu (-s 5 -c 1) captures the GEMM next
    dummy_k<<<1, 32>>>();
    // 6: layer-2 GEMM  (now the profiled launch)
    gemm_fused_k<<<GEMM_BLKS, 256>>>(obuf, W2, as2, ad2, hhbuf, NN, HH);
    // 7: layer-2 attention aggregation
    attn_agg_k<<<warps_grid, 256>>>(b2, obuf, 1);
    // 8: pool + head (+ restore zero invariant)
    poolhead_k<<<GG, 128>>>(obuf, batch, Wl, bl, out);
}

// round 13
// speedup vs baseline: 1.1232x; 1.1232x over previous
#include <cuda_runtime.h>
#include <cuda_fp16.h>
#include <math.h>
#include <stdint.h>

// Problem constants
#define NN 50000
#define EE 800000
#define FF 86
#define HH 128
#define EDD 16
#define CC 18
#define GG 64
#define NEG_SLOPE 0.2f

#define NBLK ((NN + 255) / 256)        // 196 scan blocks
#define GEMM_BLKS ((NN + 127) / 128)   // 391 gemm blocks
#define HISTB 592                       // hist blocks inside fat kernel

// ---------------- scratch (static device globals; no allocation) ----------------
// INVARIANT: d_deg, d_cur, d_sstate are all-zero at kernel_launch entry.
// (zero-initialized at module load; re-zeroed by poolhead_k at the end of every call)
__device__ int    d_deg[NN];
__device__ int    d_cur[NN];
__device__ int    d_off[NN + 1];
__device__ volatile unsigned long long d_sstate[NBLK];  // lookback: flag<<32 | total
__device__ float4 d_edge[EE];             // per-edge record: {ea1, ea2, src(bits), unused}
__device__ __half d_hh[(size_t)NN * HH];  // fp16 transformed features (gather source)
__device__ float  d_o[(size_t)NN * HH];   // layer output (fp32, gemm input)
__device__ float  d_hs[NN];
__device__ float  d_hd[NN];
__device__ float  d_v1[EDD];
__device__ float  d_v2[EDD];

// ---------------- small helpers ----------------
__device__ __forceinline__ float to_tf32(float x) {
    uint32_t u;
    asm("cvt.rna.tf32.f32 %0, %1;" : "=r"(u) : "f"(x));
    return __uint_as_float(u);
}

__device__ __forceinline__ int warp_iscan(int x, int lane) {
#pragma unroll
    for (int o = 1; o < 32; o <<= 1) {
        int y = __shfl_up_sync(0xffffffffu, x, o);
        if (lane >= o) x += y;
    }
    return x;
}

// ---------------- tf32 GEMM body (pipelined) + fused hs/hd epilogue ----------------
// hh[M,128](fp16) = A[M,K] @ B[K,128]; hs = hh@a_src; hd = hh@a_dst (fp32 from accs)
// block tile 128x128, K chunked by 32; 8 warps, warp tile 64x32 (m16n8k8 atoms).
#define KC 32
__device__ __forceinline__ void gemm_body(const float* __restrict__ A,
                                          const float* __restrict__ B,
                                          const float* __restrict__ a_src,
                                          const float* __restrict__ a_dst,
                                          __half* __restrict__ Chh,
                                          int M, int K, int blk) {
    __shared__ float As[128][KC + 4];    // stride 36
    __shared__ float Bs[KC][HH + 4];     // stride 132
    __shared__ float hs_part[4][128], hd_part[4][128];
    int tid = threadIdx.x;
    int wid = tid >> 5, lane = tid & 31;
    int mw = wid >> 2, nw = wid & 3;          // 2 x 4 warp grid
    int gp = lane >> 2, t4 = lane & 3;        // fragment coords
    int rowBase = blk * 128;

    int rl = tid >> 3;   // 0..31 (A row group)
    int kl = tid & 7;    // 0..7  (A col group)
    float  aR[16];
    float4 bR[4];

    auto loadA = [&](int kbase) {
#pragma unroll
        for (int i = 0; i < 4; i++) {
            int grow = rowBase + rl + i * 32;
            const float* arow = A + (size_t)grow * K;
#pragma unroll
            for (int j = 0; j < 4; j++) {
                int gk = kbase + kl + j * 8;
                aR[i * 4 + j] = (grow < M && gk < K) ? arow[gk] : 0.f;
            }
        }
    };
    auto loadB = [&](int kbase) {
#pragma unroll
        for (int i = 0; i < 4; i++) {
            int idx = tid + 256 * i;
            int k = idx >> 5, f4 = idx & 31;
            int gk = kbase + k;
            bR[i] = (gk < K) ? *(const float4*)&B[(size_t)gk * HH + f4 * 4]
                             : make_float4(0.f, 0.f, 0.f, 0.f);
        }
    };
    auto stsAB = [&]() {
#pragma unroll
        for (int i = 0; i < 4; i++)
#pragma unroll
            for (int j = 0; j < 4; j++)
                As[rl + i * 32][kl + j * 8] = to_tf32(aR[i * 4 + j]);
#pragma unroll
        for (int i = 0; i < 4; i++) {
            int idx = tid + 256 * i;
            int k = idx >> 5, f4 = idx & 31;
            Bs[k][f4 * 4 + 0] = to_tf32(bR[i].x);
            Bs[k][f4 * 4 + 1] = to_tf32(bR[i].y);
            Bs[k][f4 * 4 + 2] = to_tf32(bR[i].z);
            Bs[k][f4 * 4 + 3] = to_tf32(bR[i].w);
        }
    };

    float acc[4][4][4];
#pragma unroll
    for (int a = 0; a < 4; a++)
#pragma unroll
        for (int b = 0; b < 4; b++)
#pragma unroll
            for (int c = 0; c < 4; c++) acc[a][b][c] = 0.f;

    int nChunks = (K + KC - 1) / KC;
    loadA(0); loadB(0); stsAB();
    __syncthreads();

    for (int kc = 0; kc < nChunks; kc++) {
        bool more = (kc + 1) < nChunks;
        if (more) { loadA((kc + 1) * KC); loadB((kc + 1) * KC); }  // in-flight during MMA
#pragma unroll
        for (int ka = 0; ka < 4; ka++) {
            int kb = ka * 8;
            uint32_t af[4][4];
#pragma unroll
            for (int mi = 0; mi < 4; mi++) {
                int r0 = mw * 64 + mi * 16 + gp;
                af[mi][0] = __float_as_uint(As[r0][kb + t4]);
                af[mi][1] = __float_as_uint(As[r0 + 8][kb + t4]);
                af[mi][2] = __float_as_uint(As[r0][kb + t4 + 4]);
                af[mi][3] = __float_as_uint(As[r0 + 8][kb + t4 + 4]);
            }
            uint32_t bf[4][2];
#pragma unroll
            for (int ni = 0; ni < 4; ni++) {
                int c0 = nw * 32 + ni * 8 + gp;
                bf[ni][0] = __float_as_uint(Bs[kb + t4][c0]);
                bf[ni][1] = __float_as_uint(Bs[kb + t4 + 4][c0]);
            }
#pragma unroll
            for (int mi = 0; mi < 4; mi++)
#pragma unroll
                for (int ni = 0; ni < 4; ni++) {
                    asm volatile(
                        "mma.sync.aligned.m16n8k8.row.col.f32.tf32.tf32.f32 "
                        "{%0,%1,%2,%3}, {%4,%5,%6,%7}, {%8,%9}, {%0,%1,%2,%3};"
                        : "+f"(acc[mi][ni][0]), "+f"(acc[mi][ni][1]),
                          "+f"(acc[mi][ni][2]), "+f"(acc[mi][ni][3])
                        : "r"(af[mi][0]), "r"(af[mi][1]), "r"(af[mi][2]), "r"(af[mi][3]),
                          "r"(bf[ni][0]), "r"(bf[ni][1]));
                }
        }
        __syncthreads();
        if (more) { stsAB(); __syncthreads(); }
    }

    // epilogue: write fp16 C; hs/hd via quad-shuffle + smem partials (no atomics)
    float avs[8], avd[8];
#pragma unroll
    for (int ni = 0; ni < 4; ni++) {
        int c = nw * 32 + ni * 8 + 2 * t4;
        avs[ni * 2]     = __ldg(&a_src[c]);
        avs[ni * 2 + 1] = __ldg(&a_src[c + 1]);
        avd[ni * 2]     = __ldg(&a_dst[c]);
        avd[ni * 2 + 1] = __ldg(&a_dst[c + 1]);
    }
#pragma unroll
    for (int mi = 0; mi < 4; mi++) {
#pragma unroll
        for (int hf = 0; hf < 2; hf++) {
            int rl2 = mw * 64 + mi * 16 + gp + 8 * hf;
            int r = rowBase + rl2;
            float ss = 0.f, dd = 0.f;
#pragma unroll
            for (int ni = 0; ni < 4; ni++) {
                int c = nw * 32 + ni * 8 + 2 * t4;
                float v0 = acc[mi][ni][2 * hf + 0];
                float v1 = acc[mi][ni][2 * hf + 1];
                ss += v0 * avs[ni * 2] + v1 * avs[ni * 2 + 1];
                dd += v0 * avd[ni * 2] + v1 * avd[ni * 2 + 1];
                if (r < M)
                    *(__half2*)&Chh[(size_t)r * HH + c] =
                        __floats2half2_rn(v0, v1);
            }
            ss += __shfl_xor_sync(0xffffffffu, ss, 1);
            ss += __shfl_xor_sync(0xffffffffu, ss, 2);
            dd += __shfl_xor_sync(0xffffffffu, dd, 1);
            dd += __shfl_xor_sync(0xffffffffu, dd, 2);
            if (t4 == 0) { hs_part[nw][rl2] = ss; hd_part[nw][rl2] = dd; }
        }
    }
    __syncthreads();
    if (tid < 128) {
        int r = rowBase + tid;
        if (r < M) {
            d_hs[r] = hs_part[0][tid] + hs_part[1][tid] + hs_part[2][tid] + hs_part[3][tid];
            d_hd[r] = hd_part[0][tid] + hd_part[1][tid] + hd_part[2][tid] + hd_part[3][tid];
        }
    }
}

// ---------------- fat kernel: GEMM1 + degree histogram + v1/v2 precompute ----------------
__global__ __launch_bounds__(256) void histgemm_k(const int* __restrict__ dst,
                                                  const float* __restrict__ x,
                                                  const float* __restrict__ W1,
                                                  const float* __restrict__ as1,
                                                  const float* __restrict__ ad1,
                                                  const float* __restrict__ We1,
                                                  const float* __restrict__ ae1,
                                                  const float* __restrict__ We2,
                                                  const float* __restrict__ ae2) {
    int b = blockIdx.x;
    if (b < GEMM_BLKS) {
        gemm_body(x, W1, as1, ad1, d_hh, NN, FF, b);
    } else if (b < GEMM_BLKS + HISTB) {
        int hb = b - GEMM_BLKS;
        for (int e = hb * 256 + threadIdx.x; e < EE; e += HISTB * 256)
            atomicAdd(&d_deg[dst[e]], 1);
    } else {
        // v1 = We1@ae1, v2 = We2@ae2 (warp-parallel dots)
        int warp = threadIdx.x >> 5, lane = threadIdx.x & 31;
        for (int o = warp; o < 2 * EDD; o += 8) {
            int t = o & (EDD - 1);
            const float* W  = (o < EDD) ? We1 : We2;
            const float* ae = (o < EDD) ? ae1 : ae2;
            float s = 0.f;
            for (int h = lane; h < HH; h += 32) s += W[t * HH + h] * ae[h];
#pragma unroll
            for (int q = 16; q; q >>= 1) s += __shfl_xor_sync(0xffffffffu, s, q);
            if (lane == 0) ((o < EDD) ? d_v1 : d_v2)[t] = s;
        }
    }
}

// ---------------- single-pass scan with decoupled lookback ----------------
// d_sstate[b]: flag<<32 | value. flag 1 = block aggregate, 2 = inclusive prefix.
__global__ void scan_k() {
    __shared__ int ws[8];
    __shared__ int bt_s;     // block total
    __shared__ int pre_s;    // exclusive prefix of this block
    int t = threadIdx.x, lane = t & 31, warp = t >> 5;
    int b = blockIdx.x;
    int i = b * 256 + t;
    int v = (i < NN) ? d_deg[i] : 0;
    int wi = warp_iscan(v, lane);
    if (lane == 31) ws[warp] = wi;
    __syncthreads();
    if (warp == 0) {
        int s = (lane < 8) ? ws[lane] : 0;
        int si = warp_iscan(s, lane);
        if (lane < 8) ws[lane] = si - s;  // exclusive warp offsets
    }
    __syncthreads();
    int excl = ws[warp] + wi - v;
    if (t == 255) {
        int total = ws[7] + wi;
        bt_s = total;
        unsigned long long flag = (b == 0) ? 2ull : 1ull;   // block 0 publishes prefix
        d_sstate[b] = (flag << 32) | (unsigned int)total;
    }
    if (t == 0) {
        int run = 0;
        if (b > 0) {
            int j = b - 1;
            while (true) {
                unsigned long long s;
                do { s = d_sstate[j]; } while ((s >> 32) == 0ull);
                run += (int)(unsigned int)s;
                if ((s >> 32) == 2ull) break;
                j--;
            }
        }
        pre_s = run;
    }
    __syncthreads();
    if (t == 0 && b > 0)   // upgrade own state to inclusive prefix
        d_sstate[b] = (2ull << 32) | (unsigned int)(bt_s + pre_s);
    if (i < NN) d_off[i] = excl + pre_s;
    if (i == 0) d_off[NN] = EE;
}

// scatter edges into CSR-by-dst; one 16B record per edge (single scattered STG.128)
__global__ void scatter_k(const int* __restrict__ src, const int* __restrict__ dst,
                          const float* __restrict__ edge_attr) {
    int e = blockIdx.x * blockDim.x + threadIdx.x;
    if (e >= EE) return;
    int d = dst[e];
    int p = d_off[d] + atomicAdd(&d_cur[d], 1);
    const float4* ea = (const float4*)(edge_attr + (size_t)e * EDD);
    float s1 = 0.f, s2 = 0.f;
#pragma unroll
    for (int q = 0; q < 4; q++) {
        float4 xv = ea[q];
        s1 += xv.x * d_v1[q * 4 + 0] + xv.y * d_v1[q * 4 + 1]
            + xv.z * d_v1[q * 4 + 2] + xv.w * d_v1[q * 4 + 3];
        s2 += xv.x * d_v2[q * 4 + 0] + xv.y * d_v2[q * 4 + 1]
            + xv.z * d_v2[q * 4 + 2] + xv.w * d_v2[q * 4 + 3];
    }
    d_edge[p] = make_float4(s1, s2, __int_as_float(src[e]), 0.f);
}

// plain gemm launch wrapper (layer 2)
__global__ __launch_bounds__(256) void gemm_fused_k(const float* __restrict__ A,
                                                    const float* __restrict__ B,
                                                    const float* __restrict__ a_src,
                                                    const float* __restrict__ a_dst,
                                                    __half* __restrict__ Chh,
                                                    int M, int K) {
    gemm_body(A, B, a_src, a_dst, Chh, M, K, blockIdx.x);
}

// ---------------- attention aggregation: parallel logits + smem-staged gather ----------------
// One warp per dst node, chunks of 32 edges. Phase A (lane-parallel): each lane
// reads its 16B edge record (one LDG.128), computes exp(leaky(logit)) -> smem.
// Phase B (serial): read w/src as conflict-free broadcast LDS, gather fp16 rows
// (32 lanes x 8B = 256B/row), accumulate unnormalized; normalize once at end.
// Shift-free softmax (|logit| bounded); no global aw roundtrip.
__global__ void attn_agg_k(const float* __restrict__ bias, float* __restrict__ out,
                           int sel) {
    __shared__ float sw[8][32];
    __shared__ int   ssrc[8][32];
    int gt = blockIdx.x * blockDim.x + threadIdx.x;
    int n = gt >> 5, lane = gt & 31;
    if (n >= NN) return;
    int wid = (threadIdx.x >> 5);
    int b0 = d_off[n], b1 = d_off[n + 1];
    float hdn = d_hd[n];
    int fo = lane << 2;                       // 4 features per lane

    float4 acc = make_float4(0.f, 0.f, 0.f, 0.f);
    float ls = 0.f;

    for (int base = b0; base < b1; base += 32) {
        int j = base + lane;
        float ex = 0.f;
        int s = 0;
        if (j < b1) {                         // phase A: parallel logits
            float4 er = d_edge[j];            // one LDG.128
            s = __float_as_int(er.z);
            float a = d_hs[s] + hdn + (sel ? er.y : er.x);
            a = (a > 0.f) ? a : NEG_SLOPE * a;
            ex = __expf(a);
            ls += ex;
        }
        sw[wid][lane] = ex;
        ssrc[wid][lane] = s;
        __syncwarp();
        int cnt = min(b1 - base, 32);
        for (int jj = 0; jj < cnt; jj++) {    // phase B: serial gather
            float w = sw[wid][jj];            // broadcast LDS
            int   ss = ssrc[wid][jj];         // broadcast LDS
            uint2 raw = *(const uint2*)(d_hh + (size_t)ss * HH + fo);
            float2 f0 = __half22float2(*(__half2*)&raw.x);
            float2 f1 = __half22float2(*(__half2*)&raw.y);
            acc.x += w * f0.x; acc.y += w * f0.y;
            acc.z += w * f1.x; acc.w += w * f1.y;
        }
        __syncwarp();
    }
    // warp-total exp sum (phase A was lane-parallel)
#pragma unroll
    for (int o = 16; o; o >>= 1) ls += __shfl_xor_sync(0xffffffffu, ls, o);
    float inv = 1.f / fmaxf(ls, 1e-16f);

    float4 bv = *(const float4*)(bias + fo);
    float4 o4;
    o4.x = fmaxf(fmaf(acc.x, inv, bv.x), 0.f);
    o4.y = fmaxf(fmaf(acc.y, inv, bv.y), 0.f);
    o4.z = fmaxf(fmaf(acc.z, inv, bv.z), 0.f);
    o4.w = fmaxf(fmaf(acc.w, inv, bv.w), 0.f);
    *(float4*)(out + (size_t)n * HH + fo) = o4;
}

// ---------------- fused pool + head: one block per graph (batch is sorted) ----------------
// Also restores the all-zero invariant on d_deg / d_cur / d_sstate for the next call.
#define ZCHUNK ((NN + GG - 1) / GG)   // 782
__global__ void poolhead_k(const float* __restrict__ o, const int* __restrict__ batch,
                           const float* __restrict__ Wl, const float* __restrict__ bl,
                           float* __restrict__ out) {
    __shared__ float pool_s[HH];
    int g = blockIdx.x;     // 64 blocks
    int t = threadIdx.x;    // 128 threads

    // binary search the contiguous node range of graph g
    int lo, hi;
    { int a = 0, b = NN; while (a < b) { int m = (a + b) >> 1; if (batch[m] < g) a = m + 1; else b = m; } lo = a; }
    { int a = 0, b = NN; while (a < b) { int m = (a + b) >> 1; if (batch[m] < g + 1) a = m + 1; else b = m; } hi = a; }

    float m = 0.f;   // relu outputs >= 0; empty graph -> 0 (matches isfinite guard)
    for (int n = lo; n < hi; n++) m = fmaxf(m, o[(size_t)n * HH + t]);
    pool_s[t] = m;
    __syncthreads();

    // restore zero invariant for next call
    int z0 = g * ZCHUNK, z1 = min(z0 + ZCHUNK, NN);
    for (int z = z0 + t; z < z1; z += 128) { d_deg[z] = 0; d_cur[z] = 0; }
    if (g == 0) for (int z = t; z < NBLK; z += 128) d_sstate[z] = 0ull;

    // head: logits + log_softmax in warp 0
    if (t < 32) {
        float logit = -INFINITY;
        if (t < CC) {
            float s = bl[t];
#pragma unroll 8
            for (int k = 0; k < HH; k++) s += pool_s[k] * Wl[k * CC + t];
            logit = s;
        }
        float mx = logit;
#pragma unroll
        for (int q = 16; q; q >>= 1) mx = fmaxf(mx, __shfl_xor_sync(0xffffffffu, mx, q));
        float e = (t < CC) ? __expf(logit - mx) : 0.f;
        float se = e;
#pragma unroll
        for (int q = 16; q; q >>= 1) se += __shfl_xor_sync(0xffffffffu, se, q);
        float lse = mx + logf(se);
        if (t < CC) out[g * CC + t] = logit - lse;
    }
}

// ---------------- launch ----------------
extern "C" void kernel_launch(void* const* d_in, const int* in_sizes, int n_in,
                              void* d_out, int out_size) {
    const float* x         = (const float*)d_in[0];
    const int*   eidx      = (const int*)d_in[1];
    const float* edge_attr = (const float*)d_in[2];
    const int*   batch     = (const int*)d_in[3];
    const float* W1  = (const float*)d_in[4];
    const float* We1 = (const float*)d_in[5];
    const float* as1 = (const float*)d_in[6];
    const float* ad1 = (const float*)d_in[7];
    const float* ae1 = (const float*)d_in[8];
    const float* b1  = (const float*)d_in[9];
    const float* W2  = (const float*)d_in[10];
    const float* We2 = (const float*)d_in[11];
    const float* as2 = (const float*)d_in[12];
    const float* ad2 = (const float*)d_in[13];
    const float* ae2 = (const float*)d_in[14];
    const float* b2  = (const float*)d_in[15];
    const float* Wl  = (const float*)d_in[16];
    const float* bl  = (const float*)d_in[17];
    float* out = (float*)d_out;

    const int* srcp = eidx;
    const int* dstp = eidx + EE;

    __half* hhbuf; cudaGetSymbolAddress((void**)&hhbuf, d_hh);
    float*  obuf;  cudaGetSymbolAddress((void**)&obuf, d_o);

    const int warps_grid = (NN * 32 + 255) / 256;

    // 1: GEMM1 + hist + v1/v2  (independent roles, one fat kernel)
    histgemm_k<<<GEMM_BLKS + HISTB + 1, 256>>>(dstp, x, W1, as1, ad1,
                                               We1, ae1, We2, ae2);
    // 2: single-pass lookback scan  (deg -> off)
    scan_k<<<NBLK, 256>>>();
    // 3: CSR scatter + per-edge records
    scatter_k<<<(EE + 255) / 256, 256>>>(srcp, dstp, edge_attr);
    // 4: layer-1 attention aggregation
    attn_agg_k<<<warps_grid, 256>>>(b1, obuf, 0);
    // 5: layer-2 GEMM
    gemm_fused_k<<<GEMM_BLKS, 256>>>(obuf, W2, as2, ad2, hhbuf, NN, HH);
    // 6: layer-2 attention aggregation
    attn_agg_k<<<warps_grid, 256>>>(b2, obuf, 1);
    // 7: pool + head (+ restore zero invariant)
    poolhead_k<<<GG, 128>>>(obuf, batch, Wl, bl, out);
}